// round 1
// baseline (speedup 1.0000x reference)
#include <cuda_runtime.h>
#include <cstdint>
#include <cstddef>

#define TSTEPS 512
#define BATCH  64
#define DIM    512
#define HID    512
#define GDIM   2048            // 4*HID
#define GRID_BLOCKS 64
#define JB 8                   // hidden columns per recurrent block
#define HS_STRIDE 516          // padded (512+4) to kill bank conflicts
#define SG_STRIDE 36           // padded (32+4)

// ---------------- scratch (static device allocations; no cudaMalloc) -------
__device__ float g_xproj[(size_t)TSTEPS * BATCH * GDIM];  // 256 MB: x@W_ih^T + bias
__device__ float g_hbuf[2][BATCH * HID];                  // ping-pong hidden state
__device__ unsigned g_arrive;
__device__ unsigned g_epoch;

// ---------------- helpers ---------------------------------------------------
__device__ __forceinline__ float tf32r(float x) {
    uint32_t r; asm("cvt.rna.tf32.f32 %0, %1;" : "=r"(r) : "f"(x));
    return __uint_as_float(r);
}
__device__ __forceinline__ void mma_tf32(float c[4], const uint32_t a[4], const uint32_t b[2]) {
    asm volatile(
        "mma.sync.aligned.m16n8k8.row.col.f32.tf32.tf32.f32 "
        "{%0,%1,%2,%3}, {%4,%5,%6,%7}, {%8,%9}, {%0,%1,%2,%3};"
        : "+f"(c[0]), "+f"(c[1]), "+f"(c[2]), "+f"(c[3])
        : "r"(a[0]), "r"(a[1]), "r"(a[2]), "r"(a[3]), "r"(b[0]), "r"(b[1]));
}
__device__ __forceinline__ float ex2f(float x) { float y; asm("ex2.approx.f32 %0, %1;" : "=f"(y) : "f"(x)); return y; }
__device__ __forceinline__ float rcpf(float x) { float y; asm("rcp.approx.f32 %0, %1;" : "=f"(y) : "f"(x)); return y; }
__device__ __forceinline__ float sigf(float x)  { return rcpf(1.0f + ex2f(-1.4426950408889634f * x)); }
__device__ __forceinline__ float tanhf_(float x){ return 2.0f * sigf(2.0f * x) - 1.0f; }

// ---------------- grid barrier (all GRID_BLOCKS co-resident) ---------------
__device__ __forceinline__ void grid_sync(unsigned target) {
    __syncthreads();
    if (threadIdx.x == 0) {
        __threadfence();                       // make g_hbuf stores visible
        unsigned a = atomicAdd(&g_arrive, 1u);
        if (a == GRID_BLOCKS - 1u) {
            g_arrive = 0u;                     // reaches L2 before epoch bump (fence)
            __threadfence();
            atomicAdd(&g_epoch, 1u);
        } else {
            volatile unsigned* ep = &g_epoch;
            while (*ep != target) { }
        }
    }
    __syncthreads();
}

__global__ void reset_kernel() { g_arrive = 0u; g_epoch = 0u; }

// ============================================================================
// Kernel 1: x_proj[m, g] = sum_d X[m,d]*W_ih[g,d] + (b_ih[g]+b_hh[g])
// M = T*B = 32768, K = 512, N = 2048.  TF32 mma.sync, 128x128x32 tiles.
// ============================================================================
__global__ void __launch_bounds__(256) xproj_kernel(
    const float* __restrict__ X, const float* __restrict__ Wih,
    const float* __restrict__ b_ih, const float* __restrict__ b_hh)
{
    __shared__ float As[128][36];
    __shared__ float Bs[32][132];

    const int m0 = blockIdx.y * 128;
    const int n0 = blockIdx.x * 128;
    const int tid  = threadIdx.x;
    const int lane = tid & 31;
    const int warp = tid >> 5;
    const int wm = warp >> 1;       // 0..3 : 32 output rows each
    const int wn = warp & 1;        // 0..1 : 64 output cols each
    const int gid = lane >> 2;      // 0..7
    const int tig = lane & 3;       // 0..3

    float acc[2][8][4];
    #pragma unroll
    for (int mt = 0; mt < 2; mt++)
        #pragma unroll
        for (int nt = 0; nt < 8; nt++)
            #pragma unroll
            for (int q = 0; q < 4; q++) acc[mt][nt][q] = 0.0f;

    const int lr = tid >> 3;          // 0..31
    const int lc = (tid & 7) * 4;     // 0..28

    for (int k0 = 0; k0 < DIM; k0 += 32) {
        __syncthreads();
        #pragma unroll
        for (int p = 0; p < 4; p++) {
            int r = lr + p * 32;
            float4 v = *(const float4*)(X + (size_t)(m0 + r) * DIM + k0 + lc);
            As[r][lc+0] = tf32r(v.x); As[r][lc+1] = tf32r(v.y);
            As[r][lc+2] = tf32r(v.z); As[r][lc+3] = tf32r(v.w);
        }
        #pragma unroll
        for (int p = 0; p < 4; p++) {
            int n = lr + p * 32;
            float4 v = *(const float4*)(Wih + (size_t)(n0 + n) * DIM + k0 + lc);
            Bs[lc+0][n] = tf32r(v.x); Bs[lc+1][n] = tf32r(v.y);
            Bs[lc+2][n] = tf32r(v.z); Bs[lc+3][n] = tf32r(v.w);
        }
        __syncthreads();

        #pragma unroll
        for (int ks = 0; ks < 4; ks++) {
            const int kb = ks * 8;
            uint32_t a[2][4], b[8][2];
            #pragma unroll
            for (int mt = 0; mt < 2; mt++) {
                int row = wm * 32 + mt * 16;
                a[mt][0] = __float_as_uint(As[row + gid    ][kb + tig    ]);
                a[mt][1] = __float_as_uint(As[row + gid + 8][kb + tig    ]);
                a[mt][2] = __float_as_uint(As[row + gid    ][kb + tig + 4]);
                a[mt][3] = __float_as_uint(As[row + gid + 8][kb + tig + 4]);
            }
            #pragma unroll
            for (int nt = 0; nt < 8; nt++) {
                int col = wn * 64 + nt * 8 + gid;
                b[nt][0] = __float_as_uint(Bs[kb + tig    ][col]);
                b[nt][1] = __float_as_uint(Bs[kb + tig + 4][col]);
            }
            #pragma unroll
            for (int mt = 0; mt < 2; mt++)
                #pragma unroll
                for (int nt = 0; nt < 8; nt++)
                    mma_tf32(acc[mt][nt], a[mt], b[nt]);
        }
    }

    // epilogue: add bias, write fp32
    #pragma unroll
    for (int mt = 0; mt < 2; mt++) {
        #pragma unroll
        for (int nt = 0; nt < 8; nt++) {
            int row = m0 + wm * 32 + mt * 16 + gid;
            int col = n0 + wn * 64 + nt * 8 + 2 * tig;
            float bz0 = b_ih[col]     + b_hh[col];
            float bz1 = b_ih[col + 1] + b_hh[col + 1];
            float2 v0 = make_float2(acc[mt][nt][0] + bz0, acc[mt][nt][1] + bz1);
            float2 v1 = make_float2(acc[mt][nt][2] + bz0, acc[mt][nt][3] + bz1);
            *(float2*)(g_xproj + (size_t)row       * GDIM + col) = v0;
            *(float2*)(g_xproj + (size_t)(row + 8) * GDIM + col) = v1;
        }
    }
}

// ============================================================================
// Kernel 2: persistent recurrence. 64 blocks x 256 threads, 1 grid-sync/step.
// Block blk owns hidden cols j in [8*blk, 8*blk+8) for all 4 gates
// (32 W_hh rows, resident in SMEM as tf32 for the whole kernel).
// Per step: gates[64 x 32] = h[64 x 512] @ Whh_slice^T + x_proj tile, then
// elementwise gate math; c lives in SMEM, h ping-pongs in global.
// ============================================================================
__global__ void __launch_bounds__(256, 1) lstm_kernel(
    const float* __restrict__ mask, const float* __restrict__ h0,
    const float* __restrict__ Whh, float* __restrict__ out)
{
    extern __shared__ float smem[];
    float* h_s  = smem;                      // 64 x 516
    float* W_s  = h_s  + 64 * HS_STRIDE;     // 32 x 516
    float* sg   = W_s  + 32 * HS_STRIDE;     // 64 x 36 (xp stage -> gates)
    float* h0_s = sg   + 64 * SG_STRIDE;     // 512
    float* c_s  = h0_s + 512;                // 512

    const int tid  = threadIdx.x;
    const int blk  = blockIdx.x;
    const int j0   = blk * JB;
    const int lane = tid & 31;
    const int warp = tid >> 5;
    const int wm = warp >> 1;   // 0..3 : 16 rows (batch) each
    const int wn = warp & 1;    // 0..1 : 16 gate-cols each
    const int gid = lane >> 2;
    const int tig = lane & 3;

    // --- preload W_hh slice as tf32: row r = gate*8+jl -> Whh[gate*512+j0+jl][:]
    for (int i = tid; i < 32 * 128; i += 256) {
        int r  = i >> 7;                 // 0..31
        int k4 = (i & 127) * 4;
        int gate = r >> 3, jl = r & 7;
        float4 v = *(const float4*)(Whh + (size_t)(gate * HID + j0 + jl) * HID + k4);
        float* d = &W_s[r * HS_STRIDE + k4];
        d[0] = tf32r(v.x); d[1] = tf32r(v.y); d[2] = tf32r(v.z); d[3] = tf32r(v.w);
    }
    // --- h0 slice, c0 = h0 (reference passes h0 as c0), init ping buffer 0
    for (int i = tid; i < 512; i += 256) {
        int b = i >> 3, jl = i & 7;
        float v = h0[b * HID + j0 + jl];
        h0_s[i] = v;
        c_s[i]  = v;
        g_hbuf[0][b * HID + j0 + jl] = v;
    }
    unsigned target = 0;
    grid_sync(++target);

    for (int t = 0; t < TSTEPS; t++) {
        const float* hin  = g_hbuf[t & 1];
        float*       hout = g_hbuf[(t + 1) & 1];

        // load full h (other SMs wrote it -> bypass L1 with .cg), tf32-ify
        for (int i = tid; i < 64 * 128; i += 256) {
            int g4 = i * 4;
            int row = g4 >> 9, k = g4 & 511;
            float4 v = __ldcg((const float4*)(hin + g4));
            float* d = &h_s[row * HS_STRIDE + k];
            d[0] = tf32r(v.x); d[1] = tf32r(v.y); d[2] = tf32r(v.z); d[3] = tf32r(v.w);
        }
        // stage this block's x_proj tile [64 x 32] into sg (coalesced)
        const float* xp = g_xproj + (size_t)t * BATCH * GDIM;
        for (int i = tid; i < 512; i += 256) {
            int b = i >> 3;
            int q = i & 7;
            int gate = q >> 1, half = (q & 1) * 4;
            float4 v = *(const float4*)(xp + (size_t)b * GDIM + gate * HID + j0 + half);
            float* d = &sg[b * SG_STRIDE + gate * 8 + half];
            d[0] = v.x; d[1] = v.y; d[2] = v.z; d[3] = v.w;
        }
        __syncthreads();

        // accumulators init from x_proj tile
        float acc[2][4];
        {
            int row = wm * 16 + gid;
            #pragma unroll
            for (int nt = 0; nt < 2; nt++) {
                int col = wn * 16 + nt * 8 + 2 * tig;
                acc[nt][0] = sg[ row      * SG_STRIDE + col    ];
                acc[nt][1] = sg[ row      * SG_STRIDE + col + 1];
                acc[nt][2] = sg[(row + 8) * SG_STRIDE + col    ];
                acc[nt][3] = sg[(row + 8) * SG_STRIDE + col + 1];
            }
        }

        // K loop: 64 x (k=8) tf32 mma
        const float* pa  = &h_s[(wm * 16 + gid) * HS_STRIDE + tig];
        const float* pb0 = &W_s[(wn * 16 + gid) * HS_STRIDE + tig];
        const float* pb1 = pb0 + 8 * HS_STRIDE;
        #pragma unroll 8
        for (int ks = 0; ks < 64; ks++) {
            const int kb = ks * 8;
            uint32_t a[4], b0[2], b1[2];
            a[0]  = __float_as_uint(pa[kb]);
            a[1]  = __float_as_uint(pa[kb + 8 * HS_STRIDE]);
            a[2]  = __float_as_uint(pa[kb + 4]);
            a[3]  = __float_as_uint(pa[kb + 8 * HS_STRIDE + 4]);
            b0[0] = __float_as_uint(pb0[kb]);
            b0[1] = __float_as_uint(pb0[kb + 4]);
            b1[0] = __float_as_uint(pb1[kb]);
            b1[1] = __float_as_uint(pb1[kb + 4]);
            mma_tf32(acc[0], a, b0);
            mma_tf32(acc[1], a, b1);
        }
        __syncthreads();    // all acc-init reads of sg done -> safe to overwrite

        // scatter gate pre-activations to sg for recombination
        {
            int row = wm * 16 + gid;
            #pragma unroll
            for (int nt = 0; nt < 2; nt++) {
                int col = wn * 16 + nt * 8 + 2 * tig;
                sg[ row      * SG_STRIDE + col    ] = acc[nt][0];
                sg[ row      * SG_STRIDE + col + 1] = acc[nt][1];
                sg[(row + 8) * SG_STRIDE + col    ] = acc[nt][2];
                sg[(row + 8) * SG_STRIDE + col + 1] = acc[nt][3];
            }
        }
        __syncthreads();

        // elementwise LSTM cell + mask blend; write h to out + ping-pong buf
        for (int p = tid; p < 512; p += 256) {
            int b = p >> 3, jl = p & 7;
            float gi = sg[b * SG_STRIDE +      jl];
            float gf = sg[b * SG_STRIDE +  8 + jl];
            float gg = sg[b * SG_STRIDE + 16 + jl];
            float go = sg[b * SG_STRIDE + 24 + jl];
            float iv = sigf(gi), fv = sigf(gf), gv = tanhf_(gg), ov = sigf(go);
            float c = fv * c_s[p] + iv * gv;
            float h = ov * tanhf_(c);
            float m = mask[t * BATCH + b];
            float z = h0_s[p];                       // h0 == c0
            h = h * m + z * (1.0f - m);
            c = c * m + z * (1.0f - m);
            c_s[p] = c;
            hout[b * HID + j0 + jl] = h;
            out[(size_t)t * BATCH * HID + b * HID + j0 + jl] = h;
            if (t == TSTEPS - 1) {
                out[(size_t)TSTEPS * BATCH * HID             + b * HID + j0 + jl] = h;
                out[(size_t)TSTEPS * BATCH * HID + BATCH*HID + b * HID + j0 + jl] = c;
            }
        }
        grid_sync(++target);
    }
}

// ============================================================================
extern "C" void kernel_launch(void* const* d_in, const int* in_sizes, int n_in,
                              void* d_out, int out_size) {
    const float* inputs = (const float*)d_in[0];   // [512,64,512]
    const float* mask   = (const float*)d_in[1];   // [512,64]
    const float* h0     = (const float*)d_in[2];   // [64,512]
    const float* W_ih   = (const float*)d_in[3];   // [2048,512]
    const float* W_hh   = (const float*)d_in[4];   // [2048,512]
    const float* b_ih   = (const float*)d_in[5];   // [2048]
    const float* b_hh   = (const float*)d_in[6];   // [2048]
    float* out = (float*)d_out;                    // out | hT | cT (fp32)

    const int smem_bytes = (64 * HS_STRIDE + 32 * HS_STRIDE + 64 * SG_STRIDE + 1024) * 4;
    cudaFuncSetAttribute(lstm_kernel, cudaFuncAttributeMaxDynamicSharedMemorySize, smem_bytes);

    reset_kernel<<<1, 32>>>();

    dim3 xg(GDIM / 128, (TSTEPS * BATCH) / 128);   // (16, 256)
    xproj_kernel<<<xg, 256>>>(inputs, W_ih, b_ih, b_hh);

    lstm_kernel<<<GRID_BLOCKS, 256, smem_bytes>>>(mask, h0, W_hh, out);
}

// round 2
// speedup vs baseline: 1.1920x; 1.1920x over previous
#include <cuda_runtime.h>
#include <cstdint>
#include <cstddef>

#define TSTEPS 512
#define BATCH  64
#define DIM    512
#define HID    512
#define GDIM   2048            // 4*HID
#define GRID_BLOCKS 64
#define JB 8                   // hidden columns per recurrent block
#define HS_STRIDE 516          // padded (512+4) to kill bank conflicts
#define RED_B 36               // padded partial row stride
#define RED_W (64 * RED_B)     // one warp's partial tile

// ---------------- scratch (static device allocations; no cudaMalloc) -------
__device__ float g_xproj[(size_t)TSTEPS * BATCH * GDIM];  // 256 MB: x@W_ih^T + bias
__device__ float g_hbuf[2][BATCH * HID];                  // ping-pong hidden state
__device__ unsigned g_arrive;
__device__ unsigned g_epoch;

// ---------------- helpers ---------------------------------------------------
__device__ __forceinline__ float tf32r(float x) {
    uint32_t r; asm("cvt.rna.tf32.f32 %0, %1;" : "=r"(r) : "f"(x));
    return __uint_as_float(r);
}
__device__ __forceinline__ void mma_tf32(float c[4], const uint32_t a[4], const uint32_t b[2]) {
    asm volatile(
        "mma.sync.aligned.m16n8k8.row.col.f32.tf32.tf32.f32 "
        "{%0,%1,%2,%3}, {%4,%5,%6,%7}, {%8,%9}, {%0,%1,%2,%3};"
        : "+f"(c[0]), "+f"(c[1]), "+f"(c[2]), "+f"(c[3])
        : "r"(a[0]), "r"(a[1]), "r"(a[2]), "r"(a[3]), "r"(b[0]), "r"(b[1]));
}
__device__ __forceinline__ float ex2f(float x) { float y; asm("ex2.approx.f32 %0, %1;" : "=f"(y) : "f"(x)); return y; }
__device__ __forceinline__ float rcpf(float x) { float y; asm("rcp.approx.f32 %0, %1;" : "=f"(y) : "f"(x)); return y; }
__device__ __forceinline__ float sigf(float x)  { return rcpf(1.0f + ex2f(-1.4426950408889634f * x)); }
__device__ __forceinline__ float tanhf_(float x){ return 2.0f * sigf(2.0f * x) - 1.0f; }

// ---------------- grid barrier (all GRID_BLOCKS co-resident) ---------------
__device__ __forceinline__ void grid_sync(unsigned target) {
    __syncthreads();
    if (threadIdx.x == 0) {
        __threadfence();                       // make g_hbuf stores visible
        unsigned a = atomicAdd(&g_arrive, 1u);
        if (a == GRID_BLOCKS - 1u) {
            g_arrive = 0u;                     // reaches L2 before epoch bump (fence)
            __threadfence();
            atomicAdd(&g_epoch, 1u);
        } else {
            volatile unsigned* ep = &g_epoch;
            while (*ep != target) { }
        }
    }
    __syncthreads();
}

// ============================================================================
// Kernel 1: x_proj[m, g] = sum_d X[m,d]*W_ih[g,d] + (b_ih[g]+b_hh[g])
// M = T*B = 32768, K = 512, N = 2048.  TF32 mma.sync, 128x128x32 tiles.
// Also resets the grid-barrier state for the lstm kernel that follows.
// ============================================================================
__global__ void __launch_bounds__(256) xproj_kernel(
    const float* __restrict__ X, const float* __restrict__ Wih,
    const float* __restrict__ b_ih, const float* __restrict__ b_hh)
{
    if (blockIdx.x == 0 && blockIdx.y == 0 && threadIdx.x == 0) {
        g_arrive = 0u; g_epoch = 0u;
    }

    __shared__ float As[128][36];
    __shared__ float Bs[32][132];

    const int m0 = blockIdx.y * 128;
    const int n0 = blockIdx.x * 128;
    const int tid  = threadIdx.x;
    const int lane = tid & 31;
    const int warp = tid >> 5;
    const int wm = warp >> 1;       // 0..3 : 32 output rows each
    const int wn = warp & 1;        // 0..1 : 64 output cols each
    const int gid = lane >> 2;      // 0..7
    const int tig = lane & 3;       // 0..3

    float acc[2][8][4];
    #pragma unroll
    for (int mt = 0; mt < 2; mt++)
        #pragma unroll
        for (int nt = 0; nt < 8; nt++)
            #pragma unroll
            for (int q = 0; q < 4; q++) acc[mt][nt][q] = 0.0f;

    const int lr = tid >> 3;          // 0..31
    const int lc = (tid & 7) * 4;     // 0..28

    for (int k0 = 0; k0 < DIM; k0 += 32) {
        __syncthreads();
        #pragma unroll
        for (int p = 0; p < 4; p++) {
            int r = lr + p * 32;
            float4 v = *(const float4*)(X + (size_t)(m0 + r) * DIM + k0 + lc);
            As[r][lc+0] = tf32r(v.x); As[r][lc+1] = tf32r(v.y);
            As[r][lc+2] = tf32r(v.z); As[r][lc+3] = tf32r(v.w);
        }
        #pragma unroll
        for (int p = 0; p < 4; p++) {
            int n = lr + p * 32;
            float4 v = *(const float4*)(Wih + (size_t)(n0 + n) * DIM + k0 + lc);
            Bs[lc+0][n] = tf32r(v.x); Bs[lc+1][n] = tf32r(v.y);
            Bs[lc+2][n] = tf32r(v.z); Bs[lc+3][n] = tf32r(v.w);
        }
        __syncthreads();

        #pragma unroll
        for (int ks = 0; ks < 4; ks++) {
            const int kb = ks * 8;
            uint32_t a[2][4], b[8][2];
            #pragma unroll
            for (int mt = 0; mt < 2; mt++) {
                int row = wm * 32 + mt * 16;
                a[mt][0] = __float_as_uint(As[row + gid    ][kb + tig    ]);
                a[mt][1] = __float_as_uint(As[row + gid + 8][kb + tig    ]);
                a[mt][2] = __float_as_uint(As[row + gid    ][kb + tig + 4]);
                a[mt][3] = __float_as_uint(As[row + gid + 8][kb + tig + 4]);
            }
            #pragma unroll
            for (int nt = 0; nt < 8; nt++) {
                int col = wn * 64 + nt * 8 + gid;
                b[nt][0] = __float_as_uint(Bs[kb + tig    ][col]);
                b[nt][1] = __float_as_uint(Bs[kb + tig + 4][col]);
            }
            #pragma unroll
            for (int mt = 0; mt < 2; mt++)
                #pragma unroll
                for (int nt = 0; nt < 8; nt++)
                    mma_tf32(acc[mt][nt], a[mt], b[nt]);
        }
    }

    // epilogue: add bias, write fp32
    #pragma unroll
    for (int mt = 0; mt < 2; mt++) {
        #pragma unroll
        for (int nt = 0; nt < 8; nt++) {
            int row = m0 + wm * 32 + mt * 16 + gid;
            int col = n0 + wn * 64 + nt * 8 + 2 * tig;
            float bz0 = b_ih[col]     + b_hh[col];
            float bz1 = b_ih[col + 1] + b_hh[col + 1];
            float2 v0 = make_float2(acc[mt][nt][0] + bz0, acc[mt][nt][1] + bz1);
            float2 v1 = make_float2(acc[mt][nt][2] + bz0, acc[mt][nt][3] + bz1);
            *(float2*)(g_xproj + (size_t)row       * GDIM + col) = v0;
            *(float2*)(g_xproj + (size_t)(row + 8) * GDIM + col) = v1;
        }
    }
}

// ============================================================================
// Kernel 2: persistent recurrence, split-K with register-resident W_hh.
// 64 blocks x 256 threads (8 warps). Block owns JB=8 hidden cols across all
// 4 gates (32 output cols). Warp w owns K-slice [64w, 64w+64): its B
// fragments (64 regs) are loaded ONCE before the time loop. Per step each
// warp computes a full 64x32 partial with 128 mma and only 128 A-LDS, stores
// partials to padded SMEM, then 256 threads reduce 8 partials + x_proj and
// run the LSTM cell. h ping-pongs through L2; c stays in SMEM.
// ============================================================================
__global__ void __launch_bounds__(256, 1) lstm_kernel(
    const float* __restrict__ mask, const float* __restrict__ h0,
    const float* __restrict__ Whh, float* __restrict__ out)
{
    extern __shared__ float smem[];
    float* h_s  = smem;                      // 64 x 516  (also W staging at t<0)
    float* red  = h_s  + 64 * HS_STRIDE;     // 8 x 64 x 36 partials
    float* h0_s = red  + 8 * RED_W;          // 512
    float* c_s  = h0_s + 512;                // 512

    const int tid  = threadIdx.x;
    const int blk  = blockIdx.x;
    const int j0   = blk * JB;
    const int lane = tid & 31;
    const int warp = tid >> 5;               // 0..7 -> K-slice
    const int gid  = lane >> 2;              // 0..7
    const int tig  = lane & 3;               // 0..3
    const int kbase = warp * 64;

    // --- stage W_hh slice (32 rows x 512) into h_s temporarily, as tf32
    for (int i = tid; i < 32 * 128; i += 256) {
        int r  = i >> 7;                 // 0..31  (gate*8 + jl)
        int k4 = (i & 127) * 4;
        int gate = r >> 3, jl = r & 7;
        float4 v = *(const float4*)(Whh + (size_t)(gate * HID + j0 + jl) * HID + k4);
        float* d = &h_s[r * HS_STRIDE + k4];
        d[0] = tf32r(v.x); d[1] = tf32r(v.y); d[2] = tf32r(v.z); d[3] = tf32r(v.w);
    }
    // --- h0 slice, c0 = h0; publish tf32-rounded h0 to ping buffer 0
    for (int i = tid; i < 512; i += 256) {
        int b = i >> 3, jl = i & 7;
        float v = h0[b * HID + j0 + jl];
        h0_s[i] = v;
        c_s[i]  = v;
        g_hbuf[0][b * HID + j0 + jl] = tf32r(v);
    }
    __syncthreads();

    // --- preload this warp's B fragments: b[kk][nt][2], resident forever
    uint32_t breg[8][4][2];
    #pragma unroll
    for (int kk = 0; kk < 8; kk++)
        #pragma unroll
        for (int nt = 0; nt < 4; nt++) {
            const float* pb = &h_s[(nt * 8 + gid) * HS_STRIDE + kbase + kk * 8 + tig];
            breg[kk][nt][0] = __float_as_uint(pb[0]);
            breg[kk][nt][1] = __float_as_uint(pb[4]);
        }

    unsigned target = 0;
    grid_sync(++target);     // all blocks published h0; W staging may be overwritten

    const int rb  = tid >> 2;          // 0..63 batch row for reduce phase
    const int jl0 = (tid & 3) * 2;     // 0,2,4,6

    for (int t = 0; t < TSTEPS; t++) {
        const float* hin  = g_hbuf[t & 1];
        float*       hout = g_hbuf[(t + 1) & 1];

        // prefetch this thread's x_proj + mask early (DRAM latency hidden)
        const float* xp = g_xproj + (size_t)t * BATCH * GDIM + (size_t)rb * GDIM + j0 + jl0;
        float2 xq[4];
        #pragma unroll
        for (int g = 0; g < 4; g++) xq[g] = *(const float2*)(xp + g * HID);
        const float mval = mask[t * BATCH + rb];

        // stage full h (already tf32-rounded by producer) into SMEM
        for (int i = tid; i < 8192; i += 256) {
            int g4 = i * 4;
            int row = g4 >> 9, k = g4 & 511;
            float4 v = __ldcg((const float4*)(hin + g4));
            *(float4*)&h_s[row * HS_STRIDE + k] = v;
        }
        __syncthreads();

        // ---- split-K MMA: this warp covers k in [kbase, kbase+64)
        float acc[4][4][4];
        #pragma unroll
        for (int mt = 0; mt < 4; mt++)
            #pragma unroll
            for (int nt = 0; nt < 4; nt++)
                #pragma unroll
                for (int q = 0; q < 4; q++) acc[mt][nt][q] = 0.0f;

        #pragma unroll
        for (int kk = 0; kk < 8; kk++) {
            uint32_t a[4][4];
            #pragma unroll
            for (int mt = 0; mt < 4; mt++) {
                const float* pa = &h_s[(mt * 16 + gid) * HS_STRIDE + kbase + kk * 8 + tig];
                a[mt][0] = __float_as_uint(pa[0]);
                a[mt][1] = __float_as_uint(pa[8 * HS_STRIDE]);
                a[mt][2] = __float_as_uint(pa[4]);
                a[mt][3] = __float_as_uint(pa[8 * HS_STRIDE + 4]);
            }
            #pragma unroll
            for (int mt = 0; mt < 4; mt++)
                #pragma unroll
                for (int nt = 0; nt < 4; nt++)
                    mma_tf32(acc[mt][nt], a[mt], breg[kk][nt]);
        }

        // ---- store partials: red[warp][row][col]
        float* rw = red + warp * RED_W;
        #pragma unroll
        for (int mt = 0; mt < 4; mt++)
            #pragma unroll
            for (int nt = 0; nt < 4; nt++) {
                int row = mt * 16 + gid;
                int col = nt * 8 + 2 * tig;
                float* rp = &rw[row * RED_B + col];
                *(float2*)rp                 = make_float2(acc[mt][nt][0], acc[mt][nt][1]);
                *(float2*)(rp + 8 * RED_B)   = make_float2(acc[mt][nt][2], acc[mt][nt][3]);
            }
        __syncthreads();

        // ---- reduce 8 partials + x_proj, LSTM cell, mask blend
        float s[4][2];
        #pragma unroll
        for (int g = 0; g < 4; g++) { s[g][0] = xq[g].x; s[g][1] = xq[g].y; }
        #pragma unroll
        for (int w = 0; w < 8; w++) {
            const float* rr = red + w * RED_W + rb * RED_B + jl0;
            #pragma unroll
            for (int g = 0; g < 4; g++) {
                float2 v = *(const float2*)(rr + g * 8);
                s[g][0] += v.x; s[g][1] += v.y;
            }
        }
        #pragma unroll
        for (int u = 0; u < 2; u++) {
            float iv = sigf(s[0][u]);
            float fv = sigf(s[1][u]);
            float gv = tanhf_(s[2][u]);
            float ov = sigf(s[3][u]);
            int p = rb * 8 + jl0 + u;
            float c = fv * c_s[p] + iv * gv;
            float h = ov * tanhf_(c);
            float z = h0_s[p];                   // h0 == c0
            h = h * mval + z * (1.0f - mval);
            c = c * mval + z * (1.0f - mval);
            c_s[p] = c;
            int gcol = j0 + jl0 + u;
            hout[rb * HID + gcol] = tf32r(h);
            out[(size_t)t * BATCH * HID + rb * HID + gcol] = h;
            if (t == TSTEPS - 1) {
                out[(size_t)TSTEPS * BATCH * HID               + rb * HID + gcol] = h;
                out[(size_t)TSTEPS * BATCH * HID + BATCH * HID + rb * HID + gcol] = c;
            }
        }
        grid_sync(++target);
    }
}

// ============================================================================
extern "C" void kernel_launch(void* const* d_in, const int* in_sizes, int n_in,
                              void* d_out, int out_size) {
    const float* inputs = (const float*)d_in[0];   // [512,64,512]
    const float* mask   = (const float*)d_in[1];   // [512,64]
    const float* h0     = (const float*)d_in[2];   // [64,512]
    const float* W_ih   = (const float*)d_in[3];   // [2048,512]
    const float* W_hh   = (const float*)d_in[4];   // [2048,512]
    const float* b_ih   = (const float*)d_in[5];   // [2048]
    const float* b_hh   = (const float*)d_in[6];   // [2048]
    float* out = (float*)d_out;                    // out | hT | cT (fp32)

    const int smem_bytes = (64 * HS_STRIDE + 8 * RED_W + 1024) * 4;
    cudaFuncSetAttribute(lstm_kernel, cudaFuncAttributeMaxDynamicSharedMemorySize, smem_bytes);

    dim3 xg(GDIM / 128, (TSTEPS * BATCH) / 128);   // (16, 256)
    xproj_kernel<<<xg, 256>>>(inputs, W_ih, b_ih, b_hh);

    lstm_kernel<<<GRID_BLOCKS, 256, smem_bytes>>>(mask, h0, W_hh, out);
}

// round 3
// speedup vs baseline: 1.5856x; 1.3302x over previous
#include <cuda_runtime.h>
#include <cstdint>
#include <cstddef>

#define TSTEPS 512
#define BATCH  64
#define DIM    512
#define HID    512
#define GDIM   2048            // 4*HID
#define GRID_BLOCKS 64
#define JB 8                   // hidden columns per recurrent block
#define HS_STRIDE 516          // padded (512+4) to kill bank conflicts
#define RED_B 36               // padded partial row stride
#define RED_W (64 * RED_B)     // one warp's partial tile

// ---------------- scratch (static device allocations; no cudaMalloc) -------
__device__ float g_xproj[(size_t)TSTEPS * BATCH * GDIM];  // 256 MB: x@W_ih^T + bias
__device__ float g_hbuf[2][BATCH * HID];                  // ping-pong hidden state
__device__ unsigned g_cnt[TSTEPS + 1];                    // per-step arrival counters

// ---------------- helpers ---------------------------------------------------
__device__ __forceinline__ float tf32r(float x) {
    uint32_t r; asm("cvt.rna.tf32.f32 %0, %1;" : "=r"(r) : "f"(x));
    return __uint_as_float(r);
}
__device__ __forceinline__ void mma_tf32(float c[4], const uint32_t a[4], const uint32_t b[2]) {
    asm volatile(
        "mma.sync.aligned.m16n8k8.row.col.f32.tf32.tf32.f32 "
        "{%0,%1,%2,%3}, {%4,%5,%6,%7}, {%8,%9}, {%0,%1,%2,%3};"
        : "+f"(c[0]), "+f"(c[1]), "+f"(c[2]), "+f"(c[3])
        : "r"(a[0]), "r"(a[1]), "r"(a[2]), "r"(a[3]), "r"(b[0]), "r"(b[1]));
}
__device__ __forceinline__ float ex2f(float x) { float y; asm("ex2.approx.f32 %0, %1;" : "=f"(y) : "f"(x)); return y; }
__device__ __forceinline__ float rcpf(float x) { float y; asm("rcp.approx.f32 %0, %1;" : "=f"(y) : "f"(x)); return y; }
__device__ __forceinline__ float sigf(float x)  { return rcpf(1.0f + ex2f(-1.4426950408889634f * x)); }
__device__ __forceinline__ float tanhf_(float x){ return 2.0f * sigf(2.0f * x) - 1.0f; }

__device__ __forceinline__ unsigned ld_acq(const unsigned* p) {
    unsigned v; asm volatile("ld.acquire.gpu.global.u32 %0, [%1];" : "=r"(v) : "l"(p)); return v;
}
__device__ __forceinline__ void arrive_release(unsigned* p) {
    __threadfence();
    asm volatile("red.release.gpu.global.add.u32 [%0], 1;" :: "l"(p) : "memory");
}
__device__ __forceinline__ void cp16(uint32_t s, const void* g) {
    asm volatile("cp.async.cg.shared.global [%0], [%1], 16;" :: "r"(s), "l"(g));
}
__device__ __forceinline__ void cp_wait_all() {
    asm volatile("cp.async.commit_group;\n\tcp.async.wait_group 0;" ::: "memory");
}

// ============================================================================
// Kernel 1: x_proj[m, g] = sum_d X[m,d]*W_ih[g,d] + (b_ih[g]+b_hh[g])
// M = T*B = 32768, K = 512, N = 2048.  TF32 mma.sync, 128x128x32 tiles.
// Also resets the per-step arrival counters for the lstm kernel that follows.
// ============================================================================
__global__ void __launch_bounds__(256) xproj_kernel(
    const float* __restrict__ X, const float* __restrict__ Wih,
    const float* __restrict__ b_ih, const float* __restrict__ b_hh)
{
    {
        int bid = blockIdx.y * gridDim.x + blockIdx.x;
        if (threadIdx.x == 0 && bid <= TSTEPS) g_cnt[bid] = 0u;
    }

    __shared__ float As[128][36];
    __shared__ float Bs[32][132];

    const int m0 = blockIdx.y * 128;
    const int n0 = blockIdx.x * 128;
    const int tid  = threadIdx.x;
    const int lane = tid & 31;
    const int warp = tid >> 5;
    const int wm = warp >> 1;       // 0..3 : 32 output rows each
    const int wn = warp & 1;        // 0..1 : 64 output cols each
    const int gid = lane >> 2;      // 0..7
    const int tig = lane & 3;       // 0..3

    float acc[2][8][4];
    #pragma unroll
    for (int mt = 0; mt < 2; mt++)
        #pragma unroll
        for (int nt = 0; nt < 8; nt++)
            #pragma unroll
            for (int q = 0; q < 4; q++) acc[mt][nt][q] = 0.0f;

    const int lr = tid >> 3;          // 0..31
    const int lc = (tid & 7) * 4;     // 0..28

    for (int k0 = 0; k0 < DIM; k0 += 32) {
        __syncthreads();
        #pragma unroll
        for (int p = 0; p < 4; p++) {
            int r = lr + p * 32;
            float4 v = *(const float4*)(X + (size_t)(m0 + r) * DIM + k0 + lc);
            As[r][lc+0] = tf32r(v.x); As[r][lc+1] = tf32r(v.y);
            As[r][lc+2] = tf32r(v.z); As[r][lc+3] = tf32r(v.w);
        }
        #pragma unroll
        for (int p = 0; p < 4; p++) {
            int n = lr + p * 32;
            float4 v = *(const float4*)(Wih + (size_t)(n0 + n) * DIM + k0 + lc);
            Bs[lc+0][n] = tf32r(v.x); Bs[lc+1][n] = tf32r(v.y);
            Bs[lc+2][n] = tf32r(v.z); Bs[lc+3][n] = tf32r(v.w);
        }
        __syncthreads();

        #pragma unroll
        for (int ks = 0; ks < 4; ks++) {
            const int kb = ks * 8;
            uint32_t a[2][4], b[8][2];
            #pragma unroll
            for (int mt = 0; mt < 2; mt++) {
                int row = wm * 32 + mt * 16;
                a[mt][0] = __float_as_uint(As[row + gid    ][kb + tig    ]);
                a[mt][1] = __float_as_uint(As[row + gid + 8][kb + tig    ]);
                a[mt][2] = __float_as_uint(As[row + gid    ][kb + tig + 4]);
                a[mt][3] = __float_as_uint(As[row + gid + 8][kb + tig + 4]);
            }
            #pragma unroll
            for (int nt = 0; nt < 8; nt++) {
                int col = wn * 64 + nt * 8 + gid;
                b[nt][0] = __float_as_uint(Bs[kb + tig    ][col]);
                b[nt][1] = __float_as_uint(Bs[kb + tig + 4][col]);
            }
            #pragma unroll
            for (int mt = 0; mt < 2; mt++)
                #pragma unroll
                for (int nt = 0; nt < 8; nt++)
                    mma_tf32(acc[mt][nt], a[mt], b[nt]);
        }
    }

    // epilogue: add bias, write fp32
    #pragma unroll
    for (int mt = 0; mt < 2; mt++) {
        #pragma unroll
        for (int nt = 0; nt < 8; nt++) {
            int row = m0 + wm * 32 + mt * 16 + gid;
            int col = n0 + wn * 64 + nt * 8 + 2 * tig;
            float bz0 = b_ih[col]     + b_hh[col];
            float bz1 = b_ih[col + 1] + b_hh[col + 1];
            float2 v0 = make_float2(acc[mt][nt][0] + bz0, acc[mt][nt][1] + bz1);
            float2 v1 = make_float2(acc[mt][nt][2] + bz0, acc[mt][nt][3] + bz1);
            *(float2*)(g_xproj + (size_t)row       * GDIM + col) = v0;
            *(float2*)(g_xproj + (size_t)(row + 8) * GDIM + col) = v1;
        }
    }
}

// ============================================================================
// Kernel 2: persistent recurrence, split-K, register-resident W_hh, and
// per-step monotonic arrival counters instead of a central barrier.
// 64 blocks x 256 threads (8 warps). Block owns JB=8 hidden cols across all
// 4 gates (32 output cols). Warp w owns K-slice [64w, 64w+64): B fragments
// (64 regs) live in registers forever; its slice of h_s is warp-private, so
// warps poll + cp.async + mma with NO block sync. Only 2 bar.sync per step
// (around the partial reduce). out[] stores + next-step prefetch execute in
// the poll shadow after the release-arrive.
// ============================================================================
__global__ void __launch_bounds__(256, 1) lstm_kernel(
    const float* __restrict__ mask, const float* __restrict__ h0,
    const float* __restrict__ Whh, float* __restrict__ out)
{
    extern __shared__ float smem[];
    float* h_s  = smem;                      // 64 x 516  (also W staging at t<0)
    float* red  = h_s  + 64 * HS_STRIDE;     // 8 x 64 x 36 partials
    float* h0_s = red  + 8 * RED_W;          // 512
    float* c_s  = h0_s + 512;                // 512

    const int tid  = threadIdx.x;
    const int blk  = blockIdx.x;
    const int j0   = blk * JB;
    const int lane = tid & 31;
    const int warp = tid >> 5;               // 0..7 -> K-slice
    const int gid  = lane >> 2;              // 0..7
    const int tig  = lane & 3;               // 0..3
    const int kbase = warp * 64;

    // --- stage W_hh slice (32 rows x 512) into h_s temporarily, as tf32
    for (int i = tid; i < 32 * 128; i += 256) {
        int r  = i >> 7;                 // 0..31  (gate*8 + jl)
        int k4 = (i & 127) * 4;
        int gate = r >> 3, jl = r & 7;
        float4 v = *(const float4*)(Whh + (size_t)(gate * HID + j0 + jl) * HID + k4);
        float* d = &h_s[r * HS_STRIDE + k4];
        d[0] = tf32r(v.x); d[1] = tf32r(v.y); d[2] = tf32r(v.z); d[3] = tf32r(v.w);
    }
    // --- h0 slice, c0 = h0; publish tf32-rounded h0 to ping buffer 0
    for (int i = tid; i < 512; i += 256) {
        int b = i >> 3, jl = i & 7;
        float v = h0[b * HID + j0 + jl];
        h0_s[i] = v;
        c_s[i]  = v;
        g_hbuf[0][b * HID + j0 + jl] = tf32r(v);
    }
    __syncthreads();

    // --- preload this warp's B fragments: b[kk][nt][2], resident forever
    uint32_t breg[8][4][2];
    #pragma unroll
    for (int kk = 0; kk < 8; kk++)
        #pragma unroll
        for (int nt = 0; nt < 4; nt++) {
            const float* pb = &h_s[(nt * 8 + gid) * HS_STRIDE + kbase + kk * 8 + tig];
            breg[kk][nt][0] = __float_as_uint(pb[0]);
            breg[kk][nt][1] = __float_as_uint(pb[4]);
        }
    __syncthreads();
    if (tid == 0) arrive_release(&g_cnt[0]);   // h0 published

    const int rb  = tid >> 2;          // 0..63 batch row for reduce phase
    const int jl0 = (tid & 3) * 2;     // 0,2,4,6

    // smem byte address of this warp's h_s column slice (for cp.async)
    const uint32_t hss = (uint32_t)__cvta_generic_to_shared(h_s);

    // prefetch x_proj + mask for t=0
    const float* xp0 = g_xproj + (size_t)rb * GDIM + j0 + jl0;
    float2 xq[4];
    #pragma unroll
    for (int g = 0; g < 4; g++) xq[g] = *(const float2*)(xp0 + g * HID);
    float mval = mask[rb];

    for (int t = 0; t < TSTEPS; t++) {
        const float* hin  = g_hbuf[t & 1];
        float*       hout = g_hbuf[(t + 1) & 1];

        // ---- wait for all 64 blocks to have published h(t)
        while (ld_acq(&g_cnt[t]) < GRID_BLOCKS) { }

        // ---- per-warp: cp.async own K-slice [64 rows x 64 cols] into h_s
        {
            const float* src = hin + kbase;
            #pragma unroll 8
            for (int it = 0; it < 32; it++) {
                int e   = it * 32 + lane;
                int row = e >> 4;
                int c4  = (e & 15) << 2;
                cp16(hss + (uint32_t)(row * HS_STRIDE + kbase + c4) * 4,
                     src + (size_t)row * HID + c4);
            }
            cp_wait_all();
            __syncwarp();
        }

        // ---- split-K MMA: this warp covers k in [kbase, kbase+64)
        float acc[4][4][4];
        #pragma unroll
        for (int mt = 0; mt < 4; mt++)
            #pragma unroll
            for (int nt = 0; nt < 4; nt++)
                #pragma unroll
                for (int q = 0; q < 4; q++) acc[mt][nt][q] = 0.0f;

        #pragma unroll
        for (int kk = 0; kk < 8; kk++) {
            uint32_t a[4][4];
            #pragma unroll
            for (int mt = 0; mt < 4; mt++) {
                const float* pa = &h_s[(mt * 16 + gid) * HS_STRIDE + kbase + kk * 8 + tig];
                a[mt][0] = __float_as_uint(pa[0]);
                a[mt][1] = __float_as_uint(pa[8 * HS_STRIDE]);
                a[mt][2] = __float_as_uint(pa[4]);
                a[mt][3] = __float_as_uint(pa[8 * HS_STRIDE + 4]);
            }
            #pragma unroll
            for (int mt = 0; mt < 4; mt++)
                #pragma unroll
                for (int nt = 0; nt < 4; nt++)
                    mma_tf32(acc[mt][nt], a[mt], breg[kk][nt]);
        }

        // ---- store partials: red[warp][row][col]
        float* rw = red + warp * RED_W;
        #pragma unroll
        for (int mt = 0; mt < 4; mt++)
            #pragma unroll
            for (int nt = 0; nt < 4; nt++) {
                int row = mt * 16 + gid;
                int col = nt * 8 + 2 * tig;
                float* rp = &rw[row * RED_B + col];
                *(float2*)rp                 = make_float2(acc[mt][nt][0], acc[mt][nt][1]);
                *(float2*)(rp + 8 * RED_B)   = make_float2(acc[mt][nt][2], acc[mt][nt][3]);
            }
        __syncthreads();

        // ---- reduce 8 partials + x_proj, LSTM cell, mask blend, publish h
        float s[4][2];
        #pragma unroll
        for (int g = 0; g < 4; g++) { s[g][0] = xq[g].x; s[g][1] = xq[g].y; }
        #pragma unroll
        for (int w = 0; w < 8; w++) {
            const float* rr = red + w * RED_W + rb * RED_B + jl0;
            #pragma unroll
            for (int g = 0; g < 4; g++) {
                float2 v = *(const float2*)(rr + g * 8);
                s[g][0] += v.x; s[g][1] += v.y;
            }
        }
        float hv[2], cv[2];
        #pragma unroll
        for (int u = 0; u < 2; u++) {
            float iv = sigf(s[0][u]);
            float fv = sigf(s[1][u]);
            float gv = tanhf_(s[2][u]);
            float ov = sigf(s[3][u]);
            int p = rb * 8 + jl0 + u;
            float c = fv * c_s[p] + iv * gv;
            float h = ov * tanhf_(c);
            float z = h0_s[p];                   // h0 == c0
            h = h * mval + z * (1.0f - mval);
            c = c * mval + z * (1.0f - mval);
            c_s[p] = c;
            hv[u] = h; cv[u] = c;
            hout[rb * HID + j0 + jl0 + u] = tf32r(h);
        }
        __syncthreads();
        if (tid == 0) arrive_release(&g_cnt[t + 1]);

        // ---- poll shadow: out[] stores + next-step prefetch
        #pragma unroll
        for (int u = 0; u < 2; u++) {
            int gcol = j0 + jl0 + u;
            out[(size_t)t * BATCH * HID + rb * HID + gcol] = hv[u];
            if (t == TSTEPS - 1) {
                out[(size_t)TSTEPS * BATCH * HID               + rb * HID + gcol] = hv[u];
                out[(size_t)TSTEPS * BATCH * HID + BATCH * HID + rb * HID + gcol] = cv[u];
            }
        }
        if (t + 1 < TSTEPS) {
            const float* xp = g_xproj + (size_t)(t + 1) * BATCH * GDIM
                            + (size_t)rb * GDIM + j0 + jl0;
            #pragma unroll
            for (int g = 0; g < 4; g++) xq[g] = *(const float2*)(xp + g * HID);
            mval = mask[(t + 1) * BATCH + rb];
        }
    }
}

// ============================================================================
extern "C" void kernel_launch(void* const* d_in, const int* in_sizes, int n_in,
                              void* d_out, int out_size) {
    const float* inputs = (const float*)d_in[0];   // [512,64,512]
    const float* mask   = (const float*)d_in[1];   // [512,64]
    const float* h0     = (const float*)d_in[2];   // [64,512]
    const float* W_ih   = (const float*)d_in[3];   // [2048,512]
    const float* W_hh   = (const float*)d_in[4];   // [2048,512]
    const float* b_ih   = (const float*)d_in[5];   // [2048]
    const float* b_hh   = (const float*)d_in[6];   // [2048]
    float* out = (float*)d_out;                    // out | hT | cT (fp32)

    const int smem_bytes = (64 * HS_STRIDE + 8 * RED_W + 1024) * 4;
    cudaFuncSetAttribute(lstm_kernel, cudaFuncAttributeMaxDynamicSharedMemorySize, smem_bytes);

    dim3 xg(GDIM / 128, (TSTEPS * BATCH) / 128);   // (16, 256)
    xproj_kernel<<<xg, 256>>>(inputs, W_ih, b_ih, b_hh);

    lstm_kernel<<<GRID_BLOCKS, 256, smem_bytes>>>(mask, h0, W_hh, out);
}

// round 4
// speedup vs baseline: 1.7108x; 1.0790x over previous
#include <cuda_runtime.h>
#include <cstdint>
#include <cstddef>

#define TSTEPS 512
#define BATCH  64
#define DIM    512
#define HID    512
#define GDIM   2048            // 4*HID
#define GRID_BLOCKS 64
#define NGRP 8                 // producer groups (= warps per block)
#define JB 8                   // hidden columns per recurrent block
#define HS_STRIDE 516          // padded (512+4) to kill bank conflicts
#define RED_B 36               // padded partial row stride
#define RED_W (64 * RED_B)     // one warp's partial tile

// ---------------- scratch (static device allocations; no cudaMalloc) -------
__device__ float g_xproj[(size_t)TSTEPS * BATCH * GDIM];  // 256 MB: x@W_ih^T + bias
__device__ float g_hbuf[2][BATCH * HID];                  // ping-pong hidden state
// per-step, per-group arrival counters; each padded to 32B (own sector)
__device__ unsigned g_cnt[(TSTEPS + 1) * NGRP * 8];
#define CNT(t, g) (&g_cnt[(((t) * NGRP) + (g)) * 8])

// ---------------- helpers ---------------------------------------------------
__device__ __forceinline__ float tf32r(float x) {
    uint32_t r; asm("cvt.rna.tf32.f32 %0, %1;" : "=r"(r) : "f"(x));
    return __uint_as_float(r);
}
__device__ __forceinline__ void mma_tf32(float c[4], const uint32_t a[4], const uint32_t b[2]) {
    asm volatile(
        "mma.sync.aligned.m16n8k8.row.col.f32.tf32.tf32.f32 "
        "{%0,%1,%2,%3}, {%4,%5,%6,%7}, {%8,%9}, {%0,%1,%2,%3};"
        : "+f"(c[0]), "+f"(c[1]), "+f"(c[2]), "+f"(c[3])
        : "r"(a[0]), "r"(a[1]), "r"(a[2]), "r"(a[3]), "r"(b[0]), "r"(b[1]));
}
__device__ __forceinline__ float ex2f(float x) { float y; asm("ex2.approx.f32 %0, %1;" : "=f"(y) : "f"(x)); return y; }
__device__ __forceinline__ float rcpf(float x) { float y; asm("rcp.approx.f32 %0, %1;" : "=f"(y) : "f"(x)); return y; }
__device__ __forceinline__ float sigf(float x)  { return rcpf(1.0f + ex2f(-1.4426950408889634f * x)); }
__device__ __forceinline__ float tanhf_(float x){ return 2.0f * sigf(2.0f * x) - 1.0f; }

__device__ __forceinline__ unsigned ld_acq(const unsigned* p) {
    unsigned v; asm volatile("ld.acquire.gpu.global.u32 %0, [%1];" : "=r"(v) : "l"(p)); return v;
}
__device__ __forceinline__ void arrive_release(unsigned* p) {
    asm volatile("red.release.gpu.global.add.u32 [%0], 1;" :: "l"(p) : "memory");
}
__device__ __forceinline__ void cp16(uint32_t s, const void* g) {
    asm volatile("cp.async.cg.shared.global [%0], [%1], 16;" :: "r"(s), "l"(g));
}
__device__ __forceinline__ void cp_wait_all() {
    asm volatile("cp.async.commit_group;\n\tcp.async.wait_group 0;" ::: "memory");
}

// ============================================================================
// Kernel 1: x_proj[m, g] = sum_d X[m,d]*W_ih[g,d] + (b_ih[g]+b_hh[g])
// M = T*B = 32768, K = 512, N = 2048.  TF32 mma.sync, 128x128x32 tiles.
// Also resets the per-step group counters for the lstm kernel that follows.
// ============================================================================
__global__ void __launch_bounds__(256) xproj_kernel(
    const float* __restrict__ X, const float* __restrict__ Wih,
    const float* __restrict__ b_ih, const float* __restrict__ b_hh)
{
    {
        int bid = blockIdx.y * gridDim.x + blockIdx.x;      // 0..4095
        const int ncnt = (TSTEPS + 1) * NGRP;               // 4104
        if (threadIdx.x == 0) {
            if (bid < ncnt) g_cnt[bid * 8] = 0u;
            int b2 = bid + 4096;
            if (b2 < ncnt) g_cnt[b2 * 8] = 0u;
        }
    }

    __shared__ float As[128][36];
    __shared__ float Bs[32][132];

    const int m0 = blockIdx.y * 128;
    const int n0 = blockIdx.x * 128;
    const int tid  = threadIdx.x;
    const int lane = tid & 31;
    const int warp = tid >> 5;
    const int wm = warp >> 1;       // 0..3 : 32 output rows each
    const int wn = warp & 1;        // 0..1 : 64 output cols each
    const int gid = lane >> 2;      // 0..7
    const int tig = lane & 3;       // 0..3

    float acc[2][8][4];
    #pragma unroll
    for (int mt = 0; mt < 2; mt++)
        #pragma unroll
        for (int nt = 0; nt < 8; nt++)
            #pragma unroll
            for (int q = 0; q < 4; q++) acc[mt][nt][q] = 0.0f;

    const int lr = tid >> 3;          // 0..31
    const int lc = (tid & 7) * 4;     // 0..28

    for (int k0 = 0; k0 < DIM; k0 += 32) {
        __syncthreads();
        #pragma unroll
        for (int p = 0; p < 4; p++) {
            int r = lr + p * 32;
            float4 v = *(const float4*)(X + (size_t)(m0 + r) * DIM + k0 + lc);
            As[r][lc+0] = tf32r(v.x); As[r][lc+1] = tf32r(v.y);
            As[r][lc+2] = tf32r(v.z); As[r][lc+3] = tf32r(v.w);
        }
        #pragma unroll
        for (int p = 0; p < 4; p++) {
            int n = lr + p * 32;
            float4 v = *(const float4*)(Wih + (size_t)(n0 + n) * DIM + k0 + lc);
            Bs[lc+0][n] = tf32r(v.x); Bs[lc+1][n] = tf32r(v.y);
            Bs[lc+2][n] = tf32r(v.z); Bs[lc+3][n] = tf32r(v.w);
        }
        __syncthreads();

        #pragma unroll
        for (int ks = 0; ks < 4; ks++) {
            const int kb = ks * 8;
            uint32_t a[2][4], b[8][2];
            #pragma unroll
            for (int mt = 0; mt < 2; mt++) {
                int row = wm * 32 + mt * 16;
                a[mt][0] = __float_as_uint(As[row + gid    ][kb + tig    ]);
                a[mt][1] = __float_as_uint(As[row + gid + 8][kb + tig    ]);
                a[mt][2] = __float_as_uint(As[row + gid    ][kb + tig + 4]);
                a[mt][3] = __float_as_uint(As[row + gid + 8][kb + tig + 4]);
            }
            #pragma unroll
            for (int nt = 0; nt < 8; nt++) {
                int col = wn * 64 + nt * 8 + gid;
                b[nt][0] = __float_as_uint(Bs[kb + tig    ][col]);
                b[nt][1] = __float_as_uint(Bs[kb + tig + 4][col]);
            }
            #pragma unroll
            for (int mt = 0; mt < 2; mt++)
                #pragma unroll
                for (int nt = 0; nt < 8; nt++)
                    mma_tf32(acc[mt][nt], a[mt], b[nt]);
        }
    }

    // epilogue: add bias, write fp32
    #pragma unroll
    for (int mt = 0; mt < 2; mt++) {
        #pragma unroll
        for (int nt = 0; nt < 8; nt++) {
            int row = m0 + wm * 32 + mt * 16 + gid;
            int col = n0 + wn * 64 + nt * 8 + 2 * tig;
            float bz0 = b_ih[col]     + b_hh[col];
            float bz1 = b_ih[col + 1] + b_hh[col + 1];
            float2 v0 = make_float2(acc[mt][nt][0] + bz0, acc[mt][nt][1] + bz1);
            float2 v1 = make_float2(acc[mt][nt][2] + bz0, acc[mt][nt][3] + bz1);
            *(float2*)(g_xproj + (size_t)row       * GDIM + col) = v0;
            *(float2*)(g_xproj + (size_t)(row + 8) * GDIM + col) = v1;
        }
    }
}

// ============================================================================
// Kernel 2: persistent recurrence, split-K, register-resident W_hh, and
// fine-grained PER-GROUP dataflow counters (no global barrier).
// Consumer warp w's K-slice (h cols 64w..64w+63) is produced exactly by
// blocks 8w..8w+7. Each warp of block blk release-arrives on group blk>>3
// as soon as ITS OWN hout rows are stored; consumer warp w polls only
// group w to 64 (8 blocks x 8 warps). Step skew averages instead of
// synchronizing through a 64-block max.
// ============================================================================
__global__ void __launch_bounds__(256, 1) lstm_kernel(
    const float* __restrict__ mask, const float* __restrict__ h0,
    const float* __restrict__ Whh, float* __restrict__ out)
{
    extern __shared__ float smem[];
    float* h_s  = smem;                      // 64 x 516  (also W staging at t<0)
    float* red  = h_s  + 64 * HS_STRIDE;     // 8 x 64 x 36 partials
    float* h0_s = red  + 8 * RED_W;          // 512
    float* c_s  = h0_s + 512;                // 512

    const int tid  = threadIdx.x;
    const int blk  = blockIdx.x;
    const int j0   = blk * JB;
    const int lane = tid & 31;
    const int warp = tid >> 5;               // 0..7 -> K-slice & poll group
    const int grp  = blk >> 3;               // producer group this block feeds
    const int gid  = lane >> 2;              // 0..7
    const int tig  = lane & 3;               // 0..3
    const int kbase = warp * 64;

    // --- stage W_hh slice (32 rows x 512) into h_s temporarily, as tf32
    for (int i = tid; i < 32 * 128; i += 256) {
        int r  = i >> 7;                 // 0..31  (gate*8 + jl)
        int k4 = (i & 127) * 4;
        int gate = r >> 3, jl = r & 7;
        float4 v = *(const float4*)(Whh + (size_t)(gate * HID + j0 + jl) * HID + k4);
        float* d = &h_s[r * HS_STRIDE + k4];
        d[0] = tf32r(v.x); d[1] = tf32r(v.y); d[2] = tf32r(v.z); d[3] = tf32r(v.w);
    }
    // --- h0 slice, c0 = h0; publish tf32-rounded h0 to ping buffer 0
    for (int i = tid; i < 512; i += 256) {
        int b = i >> 3, jl = i & 7;
        float v = h0[b * HID + j0 + jl];
        h0_s[i] = v;
        c_s[i]  = v;
        g_hbuf[0][b * HID + j0 + jl] = tf32r(v);
    }
    __syncthreads();

    // --- preload this warp's B fragments: b[kk][nt][2], resident forever
    uint32_t breg[8][4][2];
    #pragma unroll
    for (int kk = 0; kk < 8; kk++)
        #pragma unroll
        for (int nt = 0; nt < 4; nt++) {
            const float* pb = &h_s[(nt * 8 + gid) * HS_STRIDE + kbase + kk * 8 + tig];
            breg[kk][nt][0] = __float_as_uint(pb[0]);
            breg[kk][nt][1] = __float_as_uint(pb[4]);
        }
    __syncthreads();
    if (lane == 0) arrive_release(CNT(0, grp));   // h0 published (8 arrivals/block)

    const int rb  = tid >> 2;          // 0..63 batch row for reduce phase
    const int jl0 = (tid & 3) * 2;     // 0,2,4,6

    // smem byte address of this warp's h_s column slice (for cp.async)
    const uint32_t hss = (uint32_t)__cvta_generic_to_shared(h_s);

    // prefetch x_proj + mask for t=0
    const float* xp0 = g_xproj + (size_t)rb * GDIM + j0 + jl0;
    float2 xq[4];
    #pragma unroll
    for (int g = 0; g < 4; g++) xq[g] = *(const float2*)(xp0 + g * HID);
    float mval = mask[rb];

    for (int t = 0; t < TSTEPS; t++) {
        const float* hin  = g_hbuf[t & 1];
        float*       hout = g_hbuf[(t + 1) & 1];

        // ---- wait for THIS warp's 8 producer blocks (64 warp-arrivals)
        {
            const unsigned* myc = CNT(t, warp);
            while (ld_acq(myc) < 64u) { }
        }

        // ---- per-warp: cp.async own K-slice [64 rows x 64 cols] into h_s
        {
            const float* src = hin + kbase;
            #pragma unroll 8
            for (int it = 0; it < 32; it++) {
                int e   = it * 32 + lane;
                int row = e >> 4;
                int c4  = (e & 15) << 2;
                cp16(hss + (uint32_t)(row * HS_STRIDE + kbase + c4) * 4,
                     src + (size_t)row * HID + c4);
            }
            cp_wait_all();
            __syncwarp();
        }

        // ---- split-K MMA: this warp covers k in [kbase, kbase+64)
        float acc[4][4][4];
        #pragma unroll
        for (int mt = 0; mt < 4; mt++)
            #pragma unroll
            for (int nt = 0; nt < 4; nt++)
                #pragma unroll
                for (int q = 0; q < 4; q++) acc[mt][nt][q] = 0.0f;

        #pragma unroll
        for (int kk = 0; kk < 8; kk++) {
            uint32_t a[4][4];
            #pragma unroll
            for (int mt = 0; mt < 4; mt++) {
                const float* pa = &h_s[(mt * 16 + gid) * HS_STRIDE + kbase + kk * 8 + tig];
                a[mt][0] = __float_as_uint(pa[0]);
                a[mt][1] = __float_as_uint(pa[8 * HS_STRIDE]);
                a[mt][2] = __float_as_uint(pa[4]);
                a[mt][3] = __float_as_uint(pa[8 * HS_STRIDE + 4]);
            }
            #pragma unroll
            for (int mt = 0; mt < 4; mt++)
                #pragma unroll
                for (int nt = 0; nt < 4; nt++)
                    mma_tf32(acc[mt][nt], a[mt], breg[kk][nt]);
        }

        // ---- store partials: red[warp][row][col]
        float* rw = red + warp * RED_W;
        #pragma unroll
        for (int mt = 0; mt < 4; mt++)
            #pragma unroll
            for (int nt = 0; nt < 4; nt++) {
                int row = mt * 16 + gid;
                int col = nt * 8 + 2 * tig;
                float* rp = &rw[row * RED_B + col];
                *(float2*)rp                 = make_float2(acc[mt][nt][0], acc[mt][nt][1]);
                *(float2*)(rp + 8 * RED_B)   = make_float2(acc[mt][nt][2], acc[mt][nt][3]);
            }
        __syncthreads();                       // bar A: partials complete

        // ---- reduce 8 partials + x_proj, LSTM cell, mask blend, publish h
        float s[4][2];
        #pragma unroll
        for (int g = 0; g < 4; g++) { s[g][0] = xq[g].x; s[g][1] = xq[g].y; }
        #pragma unroll
        for (int w = 0; w < 8; w++) {
            const float* rr = red + w * RED_W + rb * RED_B + jl0;
            #pragma unroll
            for (int g = 0; g < 4; g++) {
                float2 v = *(const float2*)(rr + g * 8);
                s[g][0] += v.x; s[g][1] += v.y;
            }
        }
        float hv[2], cv[2];
        #pragma unroll
        for (int u = 0; u < 2; u++) {
            float iv = sigf(s[0][u]);
            float fv = sigf(s[1][u]);
            float gv = tanhf_(s[2][u]);
            float ov = sigf(s[3][u]);
            int p = rb * 8 + jl0 + u;
            float c = fv * c_s[p] + iv * gv;
            float h = ov * tanhf_(c);
            float z = h0_s[p];                   // h0 == c0
            h = h * mval + z * (1.0f - mval);
            c = c * mval + z * (1.0f - mval);
            c_s[p] = c;
            hv[u] = h; cv[u] = c;
            hout[rb * HID + j0 + jl0 + u] = tf32r(h);
        }
        // this warp's hout rows are stored -> release-arrive immediately
        __syncwarp();
        if (lane == 0) arrive_release(CNT(t + 1, grp));

        // ---- shadow: out[] stores + next-step prefetch (overlap bar B)
        #pragma unroll
        for (int u = 0; u < 2; u++) {
            int gcol = j0 + jl0 + u;
            out[(size_t)t * BATCH * HID + rb * HID + gcol] = hv[u];
            if (t == TSTEPS - 1) {
                out[(size_t)TSTEPS * BATCH * HID               + rb * HID + gcol] = hv[u];
                out[(size_t)TSTEPS * BATCH * HID + BATCH * HID + rb * HID + gcol] = cv[u];
            }
        }
        if (t + 1 < TSTEPS) {
            const float* xp = g_xproj + (size_t)(t + 1) * BATCH * GDIM
                            + (size_t)rb * GDIM + j0 + jl0;
            #pragma unroll
            for (int g = 0; g < 4; g++) xq[g] = *(const float2*)(xp + g * HID);
            mval = mask[(t + 1) * BATCH + rb];
        }
        __syncthreads();                       // bar B: red safe to overwrite
    }
}

// ============================================================================
extern "C" void kernel_launch(void* const* d_in, const int* in_sizes, int n_in,
                              void* d_out, int out_size) {
    const float* inputs = (const float*)d_in[0];   // [512,64,512]
    const float* mask   = (const float*)d_in[1];   // [512,64]
    const float* h0     = (const float*)d_in[2];   // [64,512]
    const float* W_ih   = (const float*)d_in[3];   // [2048,512]
    const float* W_hh   = (const float*)d_in[4];   // [2048,512]
    const float* b_ih   = (const float*)d_in[5];   // [2048]
    const float* b_hh   = (const float*)d_in[6];   // [2048]
    float* out = (float*)d_out;                    // out | hT | cT (fp32)

    const int smem_bytes = (64 * HS_STRIDE + 8 * RED_W + 1024) * 4;
    cudaFuncSetAttribute(lstm_kernel, cudaFuncAttributeMaxDynamicSharedMemorySize, smem_bytes);

    dim3 xg(GDIM / 128, (TSTEPS * BATCH) / 128);   // (16, 256)
    xproj_kernel<<<xg, 256>>>(inputs, W_ih, b_ih, b_hh);

    lstm_kernel<<<GRID_BLOCKS, 256, smem_bytes>>>(mask, h0, W_hh, out);
}